// round 16
// baseline (speedup 1.0000x reference)
#include <cuda_runtime.h>

#define CD    1024
#define NTOK  2048
#define SCALE 0.0625f      // Dh^-0.5 = 1/16
#define GR    256          // grid size (<= 148*2 for co-residency)

// Scratch (static device globals; allocation-free)
__device__ float g_q0p[64 * 1024];            // q0 partials [cchunk64][j]
__device__ float g_q0[1024];                  // q0 final
__device__ float g_wk[4 * 1024];              // per-head score vectors (scaled)
__device__ float g_party[8 * 32 * 4 * 1024];  // flash partials [b][part32][h][c]
__device__ float g_partm[8 * 32 * 4];
__device__ float g_partz[8 * 32 * 4];
__device__ float g_ybar[8 * 4 * 1024];
__device__ float g_out0[8 * 1024];
__device__ float g_p1[64 * 8 * 1024];         // [cc64][b][j]
__device__ float g_p2[64 * 8 * 1024];         // [ic64][b][j]
__device__ unsigned g_barx[16][32 * 32];      // 32 line-strided sub-counters per barrier

// cp.async helpers
__device__ __forceinline__ void cp_async16(void* smem_dst, const void* gmem_src) {
    unsigned saddr = (unsigned)__cvta_generic_to_shared(smem_dst);
    asm volatile("cp.async.cg.shared.global [%0], [%1], 16;\n"
                 :: "r"(saddr), "l"(gmem_src) : "memory");
}
#define CP_COMMIT()  asm volatile("cp.async.commit_group;\n" ::: "memory")
#define CP_WAIT(n)   asm volatile("cp.async.wait_group %0;\n" :: "n"(n) : "memory")

// Global barrier with distributed arrival counters (max 8 contenders per
// counter, counters 128B apart) and warp-parallel release polling.
// All GR blocks are co-resident, so spinning is safe.
__device__ __forceinline__ void gbar(int i) {
    __syncthreads();
    if (threadIdx.x == 0) {
        __threadfence();
        atomicAdd(&g_barx[i][(blockIdx.x & 31) * 32], 1u);
    }
    if (threadIdx.x < 32) {
        unsigned s;
        do {
            unsigned v = *(volatile unsigned*)&g_barx[i][threadIdx.x * 32];
            s = v;
            #pragma unroll
            for (int d = 1; d < 32; d <<= 1)
                s += __shfl_xor_sync(0xffffffffu, s, d);
        } while (s < GR);
        __threadfence();
    }
    __syncthreads();
}

__global__ __launch_bounds__(256, 2)
void k_fused(const float* __restrict__ x,
             const float* __restrict__ tmp,
             const float* __restrict__ Wqkv,
             const float* __restrict__ bqkv,
             const float* __restrict__ Wv,
             const float* __restrict__ bv,
             float* __restrict__ out) {
    __shared__ __align__(16) char sraw[49152];   // 6-slot ring of 8 KB stages
    int blk = blockIdx.x, tid = threadIdx.x;
    int warp = tid >> 5, lane = tid & 31;

    // ======================= Phase A: q0 partials =======================
    if (blk < 64) {
        float a0 = 0.f, a1 = 0.f, a2 = 0.f, a3 = 0.f;
        for (int r = 0; r < 16; r += 4) {
            int c = blk * 16 + r;
            float t0 = tmp[c], t1 = tmp[c + 1], t2 = tmp[c + 2], t3 = tmp[c + 3];
            const float* r0 = Wqkv + (size_t)c * 3072;
            const float* r1 = r0 + 3072;
            const float* r2 = r1 + 3072;
            const float* r3 = r2 + 3072;
            float v00 = r0[tid], v01 = r0[256 + tid], v02 = r0[512 + tid], v03 = r0[768 + tid];
            float v10 = r1[tid], v11 = r1[256 + tid], v12 = r1[512 + tid], v13 = r1[768 + tid];
            float v20 = r2[tid], v21 = r2[256 + tid], v22 = r2[512 + tid], v23 = r2[768 + tid];
            float v30 = r3[tid], v31 = r3[256 + tid], v32 = r3[512 + tid], v33 = r3[768 + tid];
            a0 += t0 * v00 + t1 * v10 + t2 * v20 + t3 * v30;
            a1 += t0 * v01 + t1 * v11 + t2 * v21 + t3 * v31;
            a2 += t0 * v02 + t1 * v12 + t2 * v22 + t3 * v32;
            a3 += t0 * v03 + t1 * v13 + t2 * v23 + t3 * v33;
        }
        g_q0p[blk * 1024 + 0 * 256 + tid] = a0;
        g_q0p[blk * 1024 + 1 * 256 + tid] = a1;
        g_q0p[blk * 1024 + 2 * 256 + tid] = a2;
        g_q0p[blk * 1024 + 3 * 256 + tid] = a3;
    }
    gbar(0);

    // ======================= Phase A2: q0 reduce (64 blocks) =======================
    if (blk < 64) {
        float* sacc = (float*)sraw;        // [16 grp][16 j]
        int jl = tid & 15, grp = tid >> 4; // grp sums cc = grp*4 .. grp*4+3
        int j = blk * 16 + jl;
        const float* p = g_q0p + (size_t)grp * 4 * 1024 + j;
        float v0 = p[0], v1 = p[1024], v2 = p[2048], v3 = p[3072];
        sacc[grp * 16 + jl] = (v0 + v1) + (v2 + v3);
        __syncthreads();
        if (tid < 16) {
            float s = 0.f;
            #pragma unroll
            for (int g = 0; g < 16; ++g) s += sacc[g * 16 + tid];
            g_q0[blk * 16 + tid] = bqkv[blk * 16 + tid] + s;
        }
        __syncthreads();
    }
    gbar(1);

    // ======================= Phase B: wk =======================
    {
        float* qs = (float*)sraw;
        qs[tid] = g_q0[tid];
        qs[256 + tid] = g_q0[256 + tid];
        qs[512 + tid] = g_q0[512 + tid];
        qs[768 + tid] = g_q0[768 + tid];
        __syncthreads();
        int r = warp >> 1, halfj = warp & 1;
        int c = blk * 4 + r;
        const float* wrow = Wqkv + (size_t)c * 3072 + 1024 + halfj * 512;
        const float* qsh = qs + halfj * 512;
        float acc0 = 0.f, acc1 = 0.f;
        #pragma unroll
        for (int q = 0; q < 8; ++q) acc0 += wrow[q * 32 + lane] * qsh[q * 32 + lane];
        #pragma unroll
        for (int q = 8; q < 16; ++q) acc1 += wrow[q * 32 + lane] * qsh[q * 32 + lane];
        #pragma unroll
        for (int d = 1; d < 32; d <<= 1) {
            acc0 += __shfl_xor_sync(0xffffffffu, acc0, d);
            acc1 += __shfl_xor_sync(0xffffffffu, acc1, d);
        }
        if (lane == 0) {
            g_wk[(halfj * 2 + 0) * 1024 + c] = acc0 * SCALE;
            g_wk[(halfj * 2 + 1) * 1024 + c] = acc1 * SCALE;
        }
        __syncthreads();
    }
    gbar(2);

    // ======================= Phase C: flash =======================
    // 256 blocks: b = blk>>5, chunk = blk&31 (64 tokens). 32 stages of 2
    // tokens (8 KB), 6-slot ring, 5 stages of lookahead (commit-to-consume
    // distance = 5 stage periods -- DRAM latency can never be exposed).
    // Warp (h=warp&3, half=warp>>2) processes token `half` of each stage
    // with register-resident xv; dot uses 2 accumulators (halved FMA chain).
    {
        float4 (*ring)[512] = reinterpret_cast<float4(*)[512]>(sraw);
        int h = warp & 3, half = warp >> 2;
        int b = blk >> 5, chunk = blk & 31;

        float4 wk4[8], y4[8];
        const float4* wkp = (const float4*)g_wk + h * 256;
        #pragma unroll
        for (int k = 0; k < 8; ++k) {
            wk4[k] = wkp[lane + 32 * k];
            y4[k]  = make_float4(0.f, 0.f, 0.f, 0.f);
        }
        float m = -1e30f, Z = 0.f;

        const float4* xb = (const float4*)x + ((size_t)b * NTOK + (size_t)chunk * 64) * 256;

        #pragma unroll
        for (int s = 0; s < 5; ++s) {
            cp_async16(&ring[s][tid],       xb + (size_t)s * 512 + tid);
            cp_async16(&ring[s][tid + 256], xb + (size_t)s * 512 + 256 + tid);
            CP_COMMIT();
        }

        for (int s = 0; s < 32; ++s) {
            if (s < 28)       { CP_WAIT(4); }
            else if (s == 28) { CP_WAIT(3); }
            else if (s == 29) { CP_WAIT(2); }
            else if (s == 30) { CP_WAIT(1); }
            else              { CP_WAIT(0); }
            __syncthreads();

            // refill stage s+5 into slot of stage s-1 (free after this barrier)
            if (s + 5 < 32) {
                int sn = s + 5;
                int slot = sn % 6;
                cp_async16(&ring[slot][tid],       xb + (size_t)sn * 512 + tid);
                cp_async16(&ring[slot][tid + 256], xb + (size_t)sn * 512 + 256 + tid);
                CP_COMMIT();
            }

            const float4* xr = &ring[s % 6][half * 256];
            float4 xv[8];
            #pragma unroll
            for (int k = 0; k < 8; ++k) xv[k] = xr[lane + 32 * k];
            float pa = 0.f, pb = 0.f;
            #pragma unroll
            for (int k = 0; k < 4; ++k)
                pa += xv[k].x * wk4[k].x + xv[k].y * wk4[k].y
                    + xv[k].z * wk4[k].z + xv[k].w * wk4[k].w;
            #pragma unroll
            for (int k = 4; k < 8; ++k)
                pb += xv[k].x * wk4[k].x + xv[k].y * wk4[k].y
                    + xv[k].z * wk4[k].z + xv[k].w * wk4[k].w;
            float p = pa + pb;
            #pragma unroll
            for (int d = 1; d < 32; d <<= 1)
                p += __shfl_xor_sync(0xffffffffu, p, d);

            float mn = fmaxf(m, p);
            float wv = __expf(p - mn);
            if (mn > m) {                    // warp-uniform; taken rarely
                float f = __expf(m - mn);
                Z *= f;
                #pragma unroll
                for (int k = 0; k < 8; ++k) {
                    y4[k].x *= f; y4[k].y *= f; y4[k].z *= f; y4[k].w *= f;
                }
                m = mn;
            }
            Z += wv;
            #pragma unroll
            for (int k = 0; k < 8; ++k) {
                y4[k].x += wv * xv[k].x;
                y4[k].y += wv * xv[k].y;
                y4[k].z += wv * xv[k].z;
                y4[k].w += wv * xv[k].w;
            }
        }

        // half-merge within block (ring memory is free: CP_WAIT(0) drained)
        __syncthreads();
        float* mbuf = (float*)sraw;             // 4 heads x 1024 floats
        float* mz   = (float*)(sraw + 16384);   // 4 x {m, Z}
        if (half == 1) {
            float4* d4 = (float4*)(mbuf + h * 1024);
            #pragma unroll
            for (int k = 0; k < 8; ++k) d4[lane + 32 * k] = y4[k];
            if (lane == 0) { mz[h * 2] = m; mz[h * 2 + 1] = Z; }
        }
        __syncthreads();
        if (half == 0) {
            float m1 = mz[h * 2], Z1 = mz[h * 2 + 1];
            float mm = fmaxf(m, m1);
            float f0 = __expf(m - mm), f1 = __expf(m1 - mm);
            const float4* s4 = (const float4*)(mbuf + h * 1024);
            float4* dst = (float4*)&g_party[(((size_t)b * 32 + chunk) * 4 + h) * 1024];
            #pragma unroll
            for (int k = 0; k < 8; ++k) {
                float4 a = s4[lane + 32 * k];
                float4 o;
                o.x = y4[k].x * f0 + a.x * f1;
                o.y = y4[k].y * f0 + a.y * f1;
                o.z = y4[k].z * f0 + a.z * f1;
                o.w = y4[k].w * f0 + a.w * f1;
                dst[lane + 32 * k] = o;
            }
            if (lane == 0) {
                g_partm[(b * 32 + chunk) * 4 + h] = mm;
                g_partz[(b * 32 + chunk) * 4 + h] = Z * f0 + Z1 * f1;
            }
        }
    }
    gbar(3);

    // ======================= Phase D: combine =======================
    {
        float* red  = (float*)sraw;               // 8
        float* sm   = red + 8;                    // 32
        float* ez   = sm + 32;                    // 32
        float* coef = ez + 32;                    // 32
        float* s0p  = coef + 32;                  // 1
        float* sacc = s0p + 1;                    // 256

        int b = blk >> 5, h = (blk & 31) >> 3, slice = blk & 7;

        const float* wkh = g_wk + h * 1024;
        float pp = 0.f;
        #pragma unroll
        for (int k = 0; k < 4; ++k) pp += tmp[tid * 4 + k] * wkh[tid * 4 + k];
        #pragma unroll
        for (int d = 1; d < 32; d <<= 1) pp += __shfl_xor_sync(0xffffffffu, pp, d);
        if (lane == 0) red[warp] = pp;
        if (tid < 32) {
            sm[tid] = g_partm[(b * 32 + tid) * 4 + h];
            ez[tid] = g_partz[(b * 32 + tid) * 4 + h];
        }
        __syncthreads();
        if (tid == 0) {
            float s = 0.f;
            #pragma unroll
            for (int w = 0; w < 8; ++w) s += red[w];
            s0p[0] = s;
        }
        __syncthreads();
        float s0 = s0p[0];
        float M = s0;
        #pragma unroll
        for (int i = 0; i < 32; ++i) M = fmaxf(M, sm[i]);
        if (tid < 32) coef[tid] = __expf(sm[tid] - M);
        __syncthreads();
        float e0 = __expf(s0 - M);
        float Zt = e0;
        #pragma unroll
        for (int i = 0; i < 32; ++i) Zt += coef[i] * ez[i];
        float inv = 1.f / Zt;

        int cch = slice * 128 + (tid & 127);
        int hp  = tid >> 7;
        const float* base = g_party + (((size_t)b * 32 + hp * 16) * 4 + h) * 1024 + cch;
        const float* cf = coef + hp * 16;
        float acc = 0.f;
        #pragma unroll
        for (int i = 0; i < 16; i += 8) {
            float v0 = base[(size_t)(i + 0) * 4096];
            float v1 = base[(size_t)(i + 1) * 4096];
            float v2 = base[(size_t)(i + 2) * 4096];
            float v3 = base[(size_t)(i + 3) * 4096];
            float v4 = base[(size_t)(i + 4) * 4096];
            float v5 = base[(size_t)(i + 5) * 4096];
            float v6 = base[(size_t)(i + 6) * 4096];
            float v7 = base[(size_t)(i + 7) * 4096];
            acc += cf[i + 0] * v0 + cf[i + 1] * v1 + cf[i + 2] * v2 + cf[i + 3] * v3
                 + cf[i + 4] * v4 + cf[i + 5] * v5 + cf[i + 6] * v6 + cf[i + 7] * v7;
        }
        if (hp == 0) acc += e0 * tmp[cch];
        sacc[hp * 128 + (tid & 127)] = acc;
        __syncthreads();
        if (tid < 128)
            g_ybar[(size_t)(b * 4 + h) * 1024 + slice * 128 + tid] =
                (sacc[tid] + sacc[128 + tid]) * inv;
        __syncthreads();
    }
    gbar(4);

    // ======================= Phase E: gemv1 partials =======================
    {
        float* ys = (float*)sraw;   // [8][16]
        int jblk = blk & 3, cc = blk >> 2;
        if (tid < 128) {
            int bb = tid >> 4, cr = tid & 15;
            ys[bb * 16 + cr] = g_ybar[(size_t)(bb * 4 + jblk) * 1024 + cc * 16 + cr];
        }
        __syncthreads();
        int j = jblk * 256 + tid;
        const float* Wcol = Wqkv + 2048 + j + (size_t)cc * 16 * 3072;
        float acc[8] = {0.f, 0.f, 0.f, 0.f, 0.f, 0.f, 0.f, 0.f};
        #pragma unroll
        for (int r0 = 0; r0 < 16; r0 += 8) {
            float w0 = Wcol[(size_t)(r0 + 0) * 3072];
            float w1 = Wcol[(size_t)(r0 + 1) * 3072];
            float w2 = Wcol[(size_t)(r0 + 2) * 3072];
            float w3 = Wcol[(size_t)(r0 + 3) * 3072];
            float w4 = Wcol[(size_t)(r0 + 4) * 3072];
            float w5 = Wcol[(size_t)(r0 + 5) * 3072];
            float w6 = Wcol[(size_t)(r0 + 6) * 3072];
            float w7 = Wcol[(size_t)(r0 + 7) * 3072];
            #pragma unroll
            for (int bb = 0; bb < 8; ++bb) {
                const float* yr = ys + bb * 16 + r0;
                acc[bb] += yr[0] * w0 + yr[1] * w1 + yr[2] * w2 + yr[3] * w3
                         + yr[4] * w4 + yr[5] * w5 + yr[6] * w6 + yr[7] * w7;
            }
        }
        #pragma unroll
        for (int bb = 0; bb < 8; ++bb)
            g_p1[(size_t)(cc * 8 + bb) * 1024 + j] = acc[bb];
        __syncthreads();
    }
    gbar(5);

    // ======================= Phase F1: reduce p1 -> out0 (256 blocks) =======
    {
        float* sacc = (float*)sraw;        // [8 grp][32 j]
        int b = blk >> 5, jc = blk & 31;
        int jl = tid & 31, grp = tid >> 5; // grp sums cc = grp*8 .. grp*8+7
        int j = jc * 32 + jl;
        const float* p = g_p1 + ((size_t)(grp * 8) * 8 + b) * 1024 + j;
        float v0 = p[0 * 8192], v1 = p[1 * 8192], v2 = p[2 * 8192], v3 = p[3 * 8192];
        float v4 = p[4 * 8192], v5 = p[5 * 8192], v6 = p[6 * 8192], v7 = p[7 * 8192];
        sacc[grp * 32 + jl] = ((v0 + v1) + (v2 + v3)) + ((v4 + v5) + (v6 + v7));
        __syncthreads();
        if (tid < 32) {
            float s = 0.f;
            #pragma unroll
            for (int g = 0; g < 8; ++g) s += sacc[g * 32 + tid];
            int jj = jc * 32 + tid;
            g_out0[b * 1024 + jj] = bqkv[2048 + jj] + s;
        }
        __syncthreads();
    }
    gbar(6);

    // ======================= Phase G: gemv2 partials =======================
    {
        float* os = (float*)sraw;   // [8][16]
        int jblk = blk & 3, ic = blk >> 2;
        if (tid < 128) {
            int bb = tid >> 4, ir = tid & 15;
            os[bb * 16 + ir] = g_out0[bb * 1024 + ic * 16 + ir];
        }
        __syncthreads();
        int j = jblk * 256 + tid;
        const float* Wcol = Wv + j + (size_t)ic * 16 * 1024;
        float acc[8] = {0.f, 0.f, 0.f, 0.f, 0.f, 0.f, 0.f, 0.f};
        #pragma unroll
        for (int r0 = 0; r0 < 16; r0 += 8) {
            float w0 = Wcol[(size_t)(r0 + 0) * 1024];
            float w1 = Wcol[(size_t)(r0 + 1) * 1024];
            float w2 = Wcol[(size_t)(r0 + 2) * 1024];
            float w3 = Wcol[(size_t)(r0 + 3) * 1024];
            float w4 = Wcol[(size_t)(r0 + 4) * 1024];
            float w5 = Wcol[(size_t)(r0 + 5) * 1024];
            float w6 = Wcol[(size_t)(r0 + 6) * 1024];
            float w7 = Wcol[(size_t)(r0 + 7) * 1024];
            #pragma unroll
            for (int bb = 0; bb < 8; ++bb) {
                const float* orow = os + bb * 16 + r0;
                acc[bb] += orow[0] * w0 + orow[1] * w1 + orow[2] * w2 + orow[3] * w3
                         + orow[4] * w4 + orow[5] * w5 + orow[6] * w6 + orow[7] * w7;
            }
        }
        #pragma unroll
        for (int bb = 0; bb < 8; ++bb)
            g_p2[(size_t)(ic * 8 + bb) * 1024 + j] = acc[bb];
        __syncthreads();
    }
    gbar(7);

    // ======================= Phase H: reduce p2 + bv -> out (256 blocks) ====
    {
        float* sacc = (float*)sraw;        // [8 grp][32 j]
        int b = blk >> 5, jc = blk & 31;
        int jl = tid & 31, grp = tid >> 5;
        int j = jc * 32 + jl;
        const float* p = g_p2 + ((size_t)(grp * 8) * 8 + b) * 1024 + j;
        float v0 = p[0 * 8192], v1 = p[1 * 8192], v2 = p[2 * 8192], v3 = p[3 * 8192];
        float v4 = p[4 * 8192], v5 = p[5 * 8192], v6 = p[6 * 8192], v7 = p[7 * 8192];
        sacc[grp * 32 + jl] = ((v0 + v1) + (v2 + v3)) + ((v4 + v5) + (v6 + v7));
        __syncthreads();
        if (tid < 32) {
            float s = 0.f;
            #pragma unroll
            for (int g = 0; g < 8; ++g) s += sacc[g * 32 + tid];
            int jj = jc * 32 + tid;
            out[b * 1024 + jj] = bv[jj] + s;
        }
    }

    // ======================= Final: arrive-only barrier + counter reset =====
    __syncthreads();
    if (tid == 0) {
        __threadfence();
        atomicAdd(&g_barx[8][(blk & 31) * 32], 1u);
    }
    if (blk == 0) {
        if (tid < 32) {
            unsigned s;
            do {
                unsigned v = *(volatile unsigned*)&g_barx[8][tid * 32];
                s = v;
                #pragma unroll
                for (int d = 1; d < 32; d <<= 1)
                    s += __shfl_xor_sync(0xffffffffu, s, d);
            } while (s < GR);
        }
        __syncthreads();
        // reset all sub-counters for the next graph replay
        if (tid < 16 * 32) g_barx[tid >> 5][(tid & 31) * 32] = 0;
        __threadfence();
    }
}

// ---------------------------------------------------------------------------
extern "C" void kernel_launch(void* const* d_in, const int* in_sizes, int n_in,
                              void* d_out, int out_size) {
    const float* x    = (const float*)d_in[0];
    const float* tmp  = (const float*)d_in[1];
    const float* Wqkv = (const float*)d_in[2];
    const float* bqkv = (const float*)d_in[3];
    const float* Wv   = (const float*)d_in[4];
    const float* bv   = (const float*)d_in[5];

    k_fused<<<GR, 256>>>(x, tmp, Wqkv, bqkv, Wv, bv, (float*)d_out);
}

// round 17
// speedup vs baseline: 1.1413x; 1.1413x over previous
#include <cuda_runtime.h>

#define CD    1024
#define NTOK  2048
#define SCALE 0.0625f      // Dh^-0.5 = 1/16
#define GR    256          // grid size (<= 148*2 for co-residency)

// Scratch (static device globals; allocation-free)
__device__ float g_q0p[64 * 1024];            // q0 partials [cchunk64][j]
__device__ float g_q0[1024];                  // q0 final
__device__ float g_wk[4 * 1024];              // per-head score vectors (scaled)
__device__ float g_party[8 * 32 * 4 * 1024];  // flash partials [b][part32][h][c]
__device__ float g_partm[8 * 32 * 4];
__device__ float g_partz[8 * 32 * 4];
__device__ float g_ybar[8 * 4 * 1024];
__device__ float g_out0[8 * 1024];
__device__ float g_p1[64 * 8 * 1024];         // [cc64][b][j]
__device__ float g_p2[64 * 8 * 1024];         // [ic64][b][j]
__device__ unsigned g_bar[16];                // global barrier counters (self-resetting)

// cp.async helpers
__device__ __forceinline__ void cp_async16(void* smem_dst, const void* gmem_src) {
    unsigned saddr = (unsigned)__cvta_generic_to_shared(smem_dst);
    asm volatile("cp.async.cg.shared.global [%0], [%1], 16;\n"
                 :: "r"(saddr), "l"(gmem_src) : "memory");
}
#define CP_COMMIT()  asm volatile("cp.async.commit_group;\n" ::: "memory")
#define CP_WAIT(n)   asm volatile("cp.async.wait_group %0;\n" :: "n"(n) : "memory")
// Named barrier over 128 threads (ids 1,2; 0 is reserved for __syncthreads)
#define NBAR(id)     asm volatile("bar.sync %0, 128;" :: "r"(id) : "memory")

// Global barrier: all GR blocks co-resident, so spin is safe.
__device__ __forceinline__ void gbar(int i) {
    __syncthreads();
    if (threadIdx.x == 0) {
        __threadfence();
        atomicAdd(&g_bar[i], 1u);
        volatile unsigned* p = &g_bar[i];
        while (*p < GR) { }
        __threadfence();
    }
    __syncthreads();
}

__global__ __launch_bounds__(256, 2)
void k_fused(const float* __restrict__ x,
             const float* __restrict__ tmp,
             const float* __restrict__ Wqkv,
             const float* __restrict__ bqkv,
             const float* __restrict__ Wv,
             const float* __restrict__ bv,
             float* __restrict__ out) {
    __shared__ __align__(16) char sraw[49152];   // 3-slot ring of 16 KB stages
    int blk = blockIdx.x, tid = threadIdx.x;
    int warp = tid >> 5, lane = tid & 31;

    // ======================= Phase A: q0 partials =======================
    if (blk < 64) {
        float a0 = 0.f, a1 = 0.f, a2 = 0.f, a3 = 0.f;
        for (int r = 0; r < 16; r += 4) {
            int c = blk * 16 + r;
            float t0 = tmp[c], t1 = tmp[c + 1], t2 = tmp[c + 2], t3 = tmp[c + 3];
            const float* r0 = Wqkv + (size_t)c * 3072;
            const float* r1 = r0 + 3072;
            const float* r2 = r1 + 3072;
            const float* r3 = r2 + 3072;
            float v00 = r0[tid], v01 = r0[256 + tid], v02 = r0[512 + tid], v03 = r0[768 + tid];
            float v10 = r1[tid], v11 = r1[256 + tid], v12 = r1[512 + tid], v13 = r1[768 + tid];
            float v20 = r2[tid], v21 = r2[256 + tid], v22 = r2[512 + tid], v23 = r2[768 + tid];
            float v30 = r3[tid], v31 = r3[256 + tid], v32 = r3[512 + tid], v33 = r3[768 + tid];
            a0 += t0 * v00 + t1 * v10 + t2 * v20 + t3 * v30;
            a1 += t0 * v01 + t1 * v11 + t2 * v21 + t3 * v31;
            a2 += t0 * v02 + t1 * v12 + t2 * v22 + t3 * v32;
            a3 += t0 * v03 + t1 * v13 + t2 * v23 + t3 * v33;
        }
        g_q0p[blk * 1024 + 0 * 256 + tid] = a0;
        g_q0p[blk * 1024 + 1 * 256 + tid] = a1;
        g_q0p[blk * 1024 + 2 * 256 + tid] = a2;
        g_q0p[blk * 1024 + 3 * 256 + tid] = a3;
    }
    gbar(0);

    // ======================= Phase A2: q0 reduce (64 blocks) =======================
    if (blk < 64) {
        float* sacc = (float*)sraw;        // [16 grp][16 j]
        int jl = tid & 15, grp = tid >> 4; // grp sums cc = grp*4 .. grp*4+3
        int j = blk * 16 + jl;
        const float* p = g_q0p + (size_t)grp * 4 * 1024 + j;
        float v0 = p[0], v1 = p[1024], v2 = p[2048], v3 = p[3072];
        sacc[grp * 16 + jl] = (v0 + v1) + (v2 + v3);
        __syncthreads();
        if (tid < 16) {
            float s = 0.f;
            #pragma unroll
            for (int g = 0; g < 16; ++g) s += sacc[g * 16 + tid];
            g_q0[blk * 16 + tid] = bqkv[blk * 16 + tid] + s;
        }
        __syncthreads();
    }
    gbar(1);

    // ======================= Phase B: wk =======================
    {
        float* qs = (float*)sraw;
        qs[tid] = g_q0[tid];
        qs[256 + tid] = g_q0[256 + tid];
        qs[512 + tid] = g_q0[512 + tid];
        qs[768 + tid] = g_q0[768 + tid];
        __syncthreads();
        int r = warp >> 1, halfj = warp & 1;
        int c = blk * 4 + r;
        const float* wrow = Wqkv + (size_t)c * 3072 + 1024 + halfj * 512;
        const float* qsh = qs + halfj * 512;
        float acc0 = 0.f, acc1 = 0.f;
        #pragma unroll
        for (int q = 0; q < 8; ++q) acc0 += wrow[q * 32 + lane] * qsh[q * 32 + lane];
        #pragma unroll
        for (int q = 8; q < 16; ++q) acc1 += wrow[q * 32 + lane] * qsh[q * 32 + lane];
        #pragma unroll
        for (int d = 1; d < 32; d <<= 1) {
            acc0 += __shfl_xor_sync(0xffffffffu, acc0, d);
            acc1 += __shfl_xor_sync(0xffffffffu, acc1, d);
        }
        if (lane == 0) {
            g_wk[(halfj * 2 + 0) * 1024 + c] = acc0 * SCALE;
            g_wk[(halfj * 2 + 1) * 1024 + c] = acc1 * SCALE;
        }
        __syncthreads();
    }
    gbar(2);

    // ======================= Phase C: flash (split pipelines) ===============
    // 256 blocks: b = blk>>5, chunk = blk&31 (64 tokens). 16 stages of 4
    // tokens; the block is split into TWO independent 128-thread groups:
    //   group g = warps 4g..4g+3 (heads 0-3) fills + consumes tokens
    //   {4s+2g, 4s+2g+1} of each stage (its own 8 KB half-slot).
    // Named barriers (bar.sync g+1, 128) replace block-wide __syncthreads:
    // a slow warp in one group no longer stalls the other group.
    {
        float4 (*ring)[1024] = reinterpret_cast<float4(*)[1024]>(sraw);
        int h = warp & 3, grp = warp >> 2;
        int gtid = tid & 127;                 // thread id within group
        int b = blk >> 5, chunk = blk & 31;

        float4 wk4[8], y4[8];
        const float4* wkp = (const float4*)g_wk + h * 256;
        #pragma unroll
        for (int k = 0; k < 8; ++k) {
            wk4[k] = wkp[lane + 32 * k];
            y4[k]  = make_float4(0.f, 0.f, 0.f, 0.f);
        }
        float m = -1e30f, Z = 0.f;

        const float4* xb = (const float4*)x + ((size_t)b * NTOK + (size_t)chunk * 64) * 256;
        const float4* xg = xb + grp * 512;    // group's token stream offset

        // prologue: fill stages 0,1 (group's own half-slots)
        #pragma unroll
        for (int s = 0; s < 2; ++s) {
            float4* dst = &ring[s][grp * 512];
            const float4* src = xg + (size_t)s * 1024;
            cp_async16(&dst[gtid],       &src[gtid]);
            cp_async16(&dst[gtid + 128], &src[gtid + 128]);
            cp_async16(&dst[gtid + 256], &src[gtid + 256]);
            cp_async16(&dst[gtid + 384], &src[gtid + 384]);
            CP_COMMIT();
        }

        for (int s = 0; s < 16; ++s) {
            if (s < 15) { CP_WAIT(1); }
            else        { CP_WAIT(0); }
            NBAR(grp + 1);

            // refill stage s+2 into slot of stage s-1 (free after group barrier)
            if (s + 2 < 16) {
                int sn = s + 2;
                float4* dst = &ring[sn % 3][grp * 512];
                const float4* src = xg + (size_t)sn * 1024;
                cp_async16(&dst[gtid],       &src[gtid]);
                cp_async16(&dst[gtid + 128], &src[gtid + 128]);
                cp_async16(&dst[gtid + 256], &src[gtid + 256]);
                cp_async16(&dst[gtid + 384], &src[gtid + 384]);
                CP_COMMIT();
            }

            const float4* base = &ring[s % 3][grp * 512];
            #pragma unroll
            for (int tt = 0; tt < 2; ++tt) {
                const float4* xr = base + tt * 256;
                float4 xv[8];
                #pragma unroll
                for (int k = 0; k < 8; ++k) xv[k] = xr[lane + 32 * k];
                float pa = 0.f, pb = 0.f;
                #pragma unroll
                for (int k = 0; k < 4; ++k)
                    pa += xv[k].x * wk4[k].x + xv[k].y * wk4[k].y
                        + xv[k].z * wk4[k].z + xv[k].w * wk4[k].w;
                #pragma unroll
                for (int k = 4; k < 8; ++k)
                    pb += xv[k].x * wk4[k].x + xv[k].y * wk4[k].y
                        + xv[k].z * wk4[k].z + xv[k].w * wk4[k].w;
                float p = pa + pb;
                #pragma unroll
                for (int d = 1; d < 32; d <<= 1)
                    p += __shfl_xor_sync(0xffffffffu, p, d);

                float mn = fmaxf(m, p);
                float wv = __expf(p - mn);
                if (mn > m) {                // warp-uniform; taken rarely
                    float f = __expf(m - mn);
                    Z *= f;
                    #pragma unroll
                    for (int k = 0; k < 8; ++k) {
                        y4[k].x *= f; y4[k].y *= f; y4[k].z *= f; y4[k].w *= f;
                    }
                    m = mn;
                }
                Z += wv;
                #pragma unroll
                for (int k = 0; k < 8; ++k) {
                    y4[k].x += wv * xv[k].x;
                    y4[k].y += wv * xv[k].y;
                    y4[k].z += wv * xv[k].z;
                    y4[k].w += wv * xv[k].w;
                }
            }
        }

        // half-merge within block (block-wide barrier: both groups done)
        __syncthreads();
        float* mbuf = (float*)sraw;             // 4 heads x 1024 floats
        float* mz   = (float*)(sraw + 16384);   // 4 x {m, Z}
        if (grp == 1) {
            float4* d4 = (float4*)(mbuf + h * 1024);
            #pragma unroll
            for (int k = 0; k < 8; ++k) d4[lane + 32 * k] = y4[k];
            if (lane == 0) { mz[h * 2] = m; mz[h * 2 + 1] = Z; }
        }
        __syncthreads();
        if (grp == 0) {
            float m1 = mz[h * 2], Z1 = mz[h * 2 + 1];
            float mm = fmaxf(m, m1);
            float f0 = __expf(m - mm), f1 = __expf(m1 - mm);
            const float4* s4 = (const float4*)(mbuf + h * 1024);
            float4* dst = (float4*)&g_party[(((size_t)b * 32 + chunk) * 4 + h) * 1024];
            #pragma unroll
            for (int k = 0; k < 8; ++k) {
                float4 a = s4[lane + 32 * k];
                float4 o;
                o.x = y4[k].x * f0 + a.x * f1;
                o.y = y4[k].y * f0 + a.y * f1;
                o.z = y4[k].z * f0 + a.z * f1;
                o.w = y4[k].w * f0 + a.w * f1;
                dst[lane + 32 * k] = o;
            }
            if (lane == 0) {
                g_partm[(b * 32 + chunk) * 4 + h] = mm;
                g_partz[(b * 32 + chunk) * 4 + h] = Z * f0 + Z1 * f1;
            }
        }
    }
    gbar(3);

    // ======================= Phase D: combine =======================
    {
        float* red  = (float*)sraw;               // 8
        float* sm   = red + 8;                    // 32
        float* ez   = sm + 32;                    // 32
        float* coef = ez + 32;                    // 32
        float* s0p  = coef + 32;                  // 1
        float* sacc = s0p + 1;                    // 256

        int b = blk >> 5, h = (blk & 31) >> 3, slice = blk & 7;

        const float* wkh = g_wk + h * 1024;
        float pp = 0.f;
        #pragma unroll
        for (int k = 0; k < 4; ++k) pp += tmp[tid * 4 + k] * wkh[tid * 4 + k];
        #pragma unroll
        for (int d = 1; d < 32; d <<= 1) pp += __shfl_xor_sync(0xffffffffu, pp, d);
        if (lane == 0) red[warp] = pp;
        if (tid < 32) {
            sm[tid] = g_partm[(b * 32 + tid) * 4 + h];
            ez[tid] = g_partz[(b * 32 + tid) * 4 + h];
        }
        __syncthreads();
        if (tid == 0) {
            float s = 0.f;
            #pragma unroll
            for (int w = 0; w < 8; ++w) s += red[w];
            s0p[0] = s;
        }
        __syncthreads();
        float s0 = s0p[0];
        float M = s0;
        #pragma unroll
        for (int i = 0; i < 32; ++i) M = fmaxf(M, sm[i]);
        if (tid < 32) coef[tid] = __expf(sm[tid] - M);
        __syncthreads();
        float e0 = __expf(s0 - M);
        float Zt = e0;
        #pragma unroll
        for (int i = 0; i < 32; ++i) Zt += coef[i] * ez[i];
        float inv = 1.f / Zt;

        int cch = slice * 128 + (tid & 127);
        int hp  = tid >> 7;
        const float* base = g_party + (((size_t)b * 32 + hp * 16) * 4 + h) * 1024 + cch;
        const float* cf = coef + hp * 16;
        float acc = 0.f;
        #pragma unroll
        for (int i = 0; i < 16; i += 8) {
            float v0 = base[(size_t)(i + 0) * 4096];
            float v1 = base[(size_t)(i + 1) * 4096];
            float v2 = base[(size_t)(i + 2) * 4096];
            float v3 = base[(size_t)(i + 3) * 4096];
            float v4 = base[(size_t)(i + 4) * 4096];
            float v5 = base[(size_t)(i + 5) * 4096];
            float v6 = base[(size_t)(i + 6) * 4096];
            float v7 = base[(size_t)(i + 7) * 4096];
            acc += cf[i + 0] * v0 + cf[i + 1] * v1 + cf[i + 2] * v2 + cf[i + 3] * v3
                 + cf[i + 4] * v4 + cf[i + 5] * v5 + cf[i + 6] * v6 + cf[i + 7] * v7;
        }
        if (hp == 0) acc += e0 * tmp[cch];
        sacc[hp * 128 + (tid & 127)] = acc;
        __syncthreads();
        if (tid < 128)
            g_ybar[(size_t)(b * 4 + h) * 1024 + slice * 128 + tid] =
                (sacc[tid] + sacc[128 + tid]) * inv;
        __syncthreads();
    }
    gbar(4);

    // ======================= Phase E: gemv1 partials =======================
    {
        float* ys = (float*)sraw;   // [8][16]
        int jblk = blk & 3, cc = blk >> 2;
        if (tid < 128) {
            int bb = tid >> 4, cr = tid & 15;
            ys[bb * 16 + cr] = g_ybar[(size_t)(bb * 4 + jblk) * 1024 + cc * 16 + cr];
        }
        __syncthreads();
        int j = jblk * 256 + tid;
        const float* Wcol = Wqkv + 2048 + j + (size_t)cc * 16 * 3072;
        float acc[8] = {0.f, 0.f, 0.f, 0.f, 0.f, 0.f, 0.f, 0.f};
        #pragma unroll
        for (int r0 = 0; r0 < 16; r0 += 8) {
            float w0 = Wcol[(size_t)(r0 + 0) * 3072];
            float w1 = Wcol[(size_t)(r0 + 1) * 3072];
            float w2 = Wcol[(size_t)(r0 + 2) * 3072];
            float w3 = Wcol[(size_t)(r0 + 3) * 3072];
            float w4 = Wcol[(size_t)(r0 + 4) * 3072];
            float w5 = Wcol[(size_t)(r0 + 5) * 3072];
            float w6 = Wcol[(size_t)(r0 + 6) * 3072];
            float w7 = Wcol[(size_t)(r0 + 7) * 3072];
            #pragma unroll
            for (int bb = 0; bb < 8; ++bb) {
                const float* yr = ys + bb * 16 + r0;
                acc[bb] += yr[0] * w0 + yr[1] * w1 + yr[2] * w2 + yr[3] * w3
                         + yr[4] * w4 + yr[5] * w5 + yr[6] * w6 + yr[7] * w7;
            }
        }
        #pragma unroll
        for (int bb = 0; bb < 8; ++bb)
            g_p1[(size_t)(cc * 8 + bb) * 1024 + j] = acc[bb];
        __syncthreads();
    }
    gbar(5);

    // ======================= Phase F1: reduce p1 -> out0 (256 blocks) =======
    {
        float* sacc = (float*)sraw;        // [8 grp][32 j]
        int b = blk >> 5, jc = blk & 31;
        int jl = tid & 31, grp = tid >> 5; // grp sums cc = grp*8 .. grp*8+7
        int j = jc * 32 + jl;
        const float* p = g_p1 + ((size_t)(grp * 8) * 8 + b) * 1024 + j;
        float v0 = p[0 * 8192], v1 = p[1 * 8192], v2 = p[2 * 8192], v3 = p[3 * 8192];
        float v4 = p[4 * 8192], v5 = p[5 * 8192], v6 = p[6 * 8192], v7 = p[7 * 8192];
        sacc[grp * 32 + jl] = ((v0 + v1) + (v2 + v3)) + ((v4 + v5) + (v6 + v7));
        __syncthreads();
        if (tid < 32) {
            float s = 0.f;
            #pragma unroll
            for (int g = 0; g < 8; ++g) s += sacc[g * 32 + tid];
            int jj = jc * 32 + tid;
            g_out0[b * 1024 + jj] = bqkv[2048 + jj] + s;
        }
        __syncthreads();
    }
    gbar(6);

    // ======================= Phase G: gemv2 partials =======================
    {
        float* os = (float*)sraw;   // [8][16]
        int jblk = blk & 3, ic = blk >> 2;
        if (tid < 128) {
            int bb = tid >> 4, ir = tid & 15;
            os[bb * 16 + ir] = g_out0[bb * 1024 + ic * 16 + ir];
        }
        __syncthreads();
        int j = jblk * 256 + tid;
        const float* Wcol = Wv + j + (size_t)ic * 16 * 1024;
        float acc[8] = {0.f, 0.f, 0.f, 0.f, 0.f, 0.f, 0.f, 0.f};
        #pragma unroll
        for (int r0 = 0; r0 < 16; r0 += 8) {
            float w0 = Wcol[(size_t)(r0 + 0) * 1024];
            float w1 = Wcol[(size_t)(r0 + 1) * 1024];
            float w2 = Wcol[(size_t)(r0 + 2) * 1024];
            float w3 = Wcol[(size_t)(r0 + 3) * 1024];
            float w4 = Wcol[(size_t)(r0 + 4) * 1024];
            float w5 = Wcol[(size_t)(r0 + 5) * 1024];
            float w6 = Wcol[(size_t)(r0 + 6) * 1024];
            float w7 = Wcol[(size_t)(r0 + 7) * 1024];
            #pragma unroll
            for (int bb = 0; bb < 8; ++bb) {
                const float* orow = os + bb * 16 + r0;
                acc[bb] += orow[0] * w0 + orow[1] * w1 + orow[2] * w2 + orow[3] * w3
                         + orow[4] * w4 + orow[5] * w5 + orow[6] * w6 + orow[7] * w7;
            }
        }
        #pragma unroll
        for (int bb = 0; bb < 8; ++bb)
            g_p2[(size_t)(ic * 8 + bb) * 1024 + j] = acc[bb];
        __syncthreads();
    }
    gbar(7);

    // ======================= Phase H: reduce p2 + bv -> out (256 blocks) ====
    {
        float* sacc = (float*)sraw;        // [8 grp][32 j]
        int b = blk >> 5, jc = blk & 31;
        int jl = tid & 31, grp = tid >> 5;
        int j = jc * 32 + jl;
        const float* p = g_p2 + ((size_t)(grp * 8) * 8 + b) * 1024 + j;
        float v0 = p[0 * 8192], v1 = p[1 * 8192], v2 = p[2 * 8192], v3 = p[3 * 8192];
        float v4 = p[4 * 8192], v5 = p[5 * 8192], v6 = p[6 * 8192], v7 = p[7 * 8192];
        sacc[grp * 32 + jl] = ((v0 + v1) + (v2 + v3)) + ((v4 + v5) + (v6 + v7));
        __syncthreads();
        if (tid < 32) {
            float s = 0.f;
            #pragma unroll
            for (int g = 0; g < 8; ++g) s += sacc[g * 32 + tid];
            int jj = jc * 32 + tid;
            out[b * 1024 + jj] = bv[jj] + s;
        }
    }

    // ======================= Final: arrive-only barrier + counter reset =====
    __syncthreads();
    if (tid == 0) {
        __threadfence();
        atomicAdd(&g_bar[8], 1u);
    }
    if (blk == 0 && tid == 0) {
        volatile unsigned* p = &g_bar[8];
        while (*p < GR) { }
        #pragma unroll
        for (int i = 0; i < 16; ++i) g_bar[i] = 0;
        __threadfence();
    }
}

// ---------------------------------------------------------------------------
extern "C" void kernel_launch(void* const* d_in, const int* in_sizes, int n_in,
                              void* d_out, int out_size) {
    const float* x    = (const float*)d_in[0];
    const float* tmp  = (const float*)d_in[1];
    const float* Wqkv = (const float*)d_in[2];
    const float* bqkv = (const float*)d_in[3];
    const float* Wv   = (const float*)d_in[4];
    const float* bv   = (const float*)d_in[5];

    k_fused<<<GR, 256>>>(x, tmp, Wqkv, bqkv, Wv, bv, (float*)d_out);
}